// round 13
// baseline (speedup 1.0000x reference)
#include <cuda_runtime.h>
#include <cuda_fp16.h>
#include <cstdint>

// ---------------- problem constants ----------------
#define NTOK 32768
#define DIN  512
#define DFF  1024
#define DFFC 512
#define NT   8
#define MAXTILES 264

#define KT  64           // K-tile in halves
#define RSA 72           // A smem row stride (halves): 144B, 16B-aligned, ldsm conflict-free
#define RSB 136          // B smem row stride (halves): 272B, 16B-aligned, ldsm conflict-free
#define STA (128 * RSA)  // halves per A stage  (9216)
#define STB (64 * RSB)   // halves per B stage  (8704)
#define SMEM_DYN (2 * (STA + STB) * 2)   // 71680 bytes -> 2 CTA/SM
#define STAGE_BYTES (128 * 128 + 64 * 256)   // 32768 per stage (A rows + B rows)

// ---------------- device scratch ----------------
__device__ __half g_xh  [NTOK * DIN];        // x fp16
__device__ __half g_wpre[DIN * DFF];         // W_pre fp16 (natural [k][n])
__device__ __half g_wtyp[NT * DFF * DIN];    // W_types fp16 (natural [t][k][n])
__device__ __half g_wc1 [DIN * DFFC];        // W_c1 fp16 (natural [k][n])
__device__ __half g_mid [NTOK * DFF];        // relu(x @ W_pre)
__device__ __half g_xnew[NTOK * DIN];        // x + relu(mid @ Wt)
__device__ float  g_part[NTOK * 4];          // per-N-slice partial dots
__device__ int    g_perm[NTOK];
__device__ int    g_cnt[NT], g_cursor[NT];
__device__ int    g_tick[256];               // gemm2 per-M-tile completion tickets

// ---------------- helpers ----------------
static __device__ __forceinline__ uint32_t smem_u32(const void* p) {
    uint32_t a;
    asm("{ .reg .u64 t; cvta.to.shared.u64 t, %1; cvt.u32.u64 %0, t; }" : "=r"(a) : "l"(p));
    return a;
}
// one-instruction bulk copy gmem->smem, completion via mbarrier complete_tx
static __device__ __forceinline__ void bulkcp(uint32_t dst, const void* src, uint32_t bytes,
                                              uint32_t mbar) {
    asm volatile("cp.async.bulk.shared::cluster.global.mbarrier::complete_tx::bytes "
                 "[%0], [%1], %2, [%3];"
                 :: "r"(dst), "l"(src), "r"(bytes), "r"(mbar) : "memory");
}
#define MBAR_INIT(mb, c) \
    asm volatile("mbarrier.init.shared.b64 [%0], %1;" :: "r"((uint32_t)(mb)), "r"((uint32_t)(c)) : "memory")
#define MBAR_EXPECT(mb, bytes) \
    asm volatile("mbarrier.arrive.expect_tx.shared.b64 _, [%0], %1;" \
                 :: "r"((uint32_t)(mb)), "r"((uint32_t)(bytes)) : "memory")
#define MBAR_WAIT(mb, ph) do { \
    uint32_t _m = (uint32_t)(mb); uint32_t _p = (uint32_t)(ph); uint32_t _d; \
    asm volatile("{\n\t.reg .pred p;\n\t" \
        "mbarrier.try_wait.parity.acquire.cta.shared::cta.b64 p, [%1], %2;\n\t" \
        "selp.b32 %0, 1, 0, p;\n\t}" : "=r"(_d) : "r"(_m), "r"(_p) : "memory"); \
    if (!_d) { \
        asm volatile("{\n\t.reg .pred P1;\n\t" \
            "WL_%=:\n\t" \
            "mbarrier.try_wait.parity.acquire.cta.shared::cta.b64 P1, [%0], %1, 0x989680;\n\t" \
            "@P1 bra.uni WD_%=;\n\t" \
            "bra.uni WL_%=;\n\t" \
            "WD_%=:\n\t}" :: "r"(_m), "r"(_p) : "memory"); \
    } } while (0)

static __device__ __forceinline__ void ldsm4(uint32_t* r, uint32_t a) {
    asm volatile("ldmatrix.sync.aligned.m8n8.x4.shared.b16 {%0,%1,%2,%3}, [%4];"
                 : "=r"(r[0]), "=r"(r[1]), "=r"(r[2]), "=r"(r[3]) : "r"(a));
}
static __device__ __forceinline__ void ldsm4t(uint32_t* r, uint32_t a) {
    asm volatile("ldmatrix.sync.aligned.m8n8.x4.trans.shared.b16 {%0,%1,%2,%3}, [%4];"
                 : "=r"(r[0]), "=r"(r[1]), "=r"(r[2]), "=r"(r[3]) : "r"(a));
}
static __device__ __forceinline__ void mma16816(float* d, const uint32_t* a, const uint32_t* b) {
    asm volatile("mma.sync.aligned.m16n8k16.row.col.f32.f16.f16.f32 "
                 "{%0,%1,%2,%3}, {%4,%5,%6,%7}, {%8,%9}, {%0,%1,%2,%3};"
                 : "+f"(d[0]), "+f"(d[1]), "+f"(d[2]), "+f"(d[3])
                 : "r"(a[0]), "r"(a[1]), "r"(a[2]), "r"(a[3]), "r"(b[0]), "r"(b[1]));
}

// ---------------- prep: fp32 -> fp16 converts + histogram ----------------
__global__ void prep_kernel(const float* __restrict__ x, const float* __restrict__ wp,
                            const float* __restrict__ wt, const float* __restrict__ wc,
                            const int* __restrict__ tr) {
    __shared__ int cnt[NT];
    __shared__ int det;
    int tid = threadIdx.x;
    int g = blockIdx.x * blockDim.x + tid;
    int nth = gridDim.x * blockDim.x;
    if (g < NT) { g_cnt[g] = 0; g_cursor[g] = 0; }
    if (g < 256) g_tick[g] = 0;

    if (blockIdx.x < 128) {
        if (tid < NT) cnt[tid] = 0;
        if (tid == 0) det = 0;
        __syncthreads();
        // dtype sniff: int64 (LE) => odd int32 words are all zero (types < 8)
        if (tr[2 * tid + 1]) atomicOr(&det, 1);
        __syncthreads();
        int stride = det ? 1 : 2;
        int i = blockIdx.x * 256 + tid;
        atomicAdd(&cnt[tr[i * stride] & 7], 1);
        __syncthreads();
        if (tid < NT) atomicAdd(&g_cnt[tid], cnt[tid]);
    }

    for (int i = g; i < NTOK * DIN / 4; i += nth) {
        float4 v = ((const float4*)x)[i];
        ((__half2*)g_xh)[2 * i]     = __floats2half2_rn(v.x, v.y);
        ((__half2*)g_xh)[2 * i + 1] = __floats2half2_rn(v.z, v.w);
    }
    for (int i = g; i < DIN * DFF / 4; i += nth) {
        float4 v = ((const float4*)wp)[i];
        ((__half2*)g_wpre)[2 * i]     = __floats2half2_rn(v.x, v.y);
        ((__half2*)g_wpre)[2 * i + 1] = __floats2half2_rn(v.z, v.w);
    }
    for (int i = g; i < NT * DFF * DIN / 4; i += nth) {
        float4 v = ((const float4*)wt)[i];
        ((__half2*)g_wtyp)[2 * i]     = __floats2half2_rn(v.x, v.y);
        ((__half2*)g_wtyp)[2 * i + 1] = __floats2half2_rn(v.z, v.w);
    }
    for (int i = g; i < DIN * DFFC / 4; i += nth) {
        float4 v = ((const float4*)wc)[i];
        ((__half2*)g_wc1)[2 * i]     = __floats2half2_rn(v.x, v.y);
        ((__half2*)g_wc1)[2 * i + 1] = __floats2half2_rn(v.z, v.w);
    }
}

__global__ void scatter_kernel(const int* __restrict__ tr) {  // grid 128 x 256
    __shared__ int cnt[NT], base[NT];
    __shared__ int det;
    int tid = threadIdx.x;
    if (tid < NT) cnt[tid] = 0;
    if (tid == 0) det = 0;
    __syncthreads();
    if (tr[2 * tid + 1]) atomicOr(&det, 1);
    __syncthreads();
    int stride = det ? 1 : 2;
    int i = blockIdx.x * 256 + tid;
    int t = tr[i * stride] & 7;
    int ls = atomicAdd(&cnt[t], 1);
    __syncthreads();
    if (tid < NT) {
        int pre = 0;
#pragma unroll
        for (int j = 0; j < NT; j++) if (j < tid) pre += g_cnt[j];
        base[tid] = pre + atomicAdd(&g_cursor[tid], cnt[tid]);
    }
    __syncthreads();
    g_perm[base[t] + ls] = i;
}

// ---------------- 128x128 tile GEMM, 8 warps of 32x64, 2-stage, cp.async.bulk ----------------
// MODE 0: mid  = relu(xh @ wpre)            NK=8,  N=1024
// MODE 1: xnew = x + relu(mid_g @ wtyp[t])  NK=16, N=512, gathered rows (in-kernel plan)
// MODE 2: out partials via ticket           NK=8,  N=512, fused GEMV + final sum
template<int MODE, int NK>
__global__ void __launch_bounds__(256, 2) gemm_kernel(const float* __restrict__ x,
                                                      const float* __restrict__ wc2,
                                                      float* __restrict__ out) {
    extern __shared__ __half smem[];
    __half* smA = smem;             // [2][STA]
    __half* smB = smem + 2 * STA;   // [2][STB]
    __shared__ int tok[128];
    __shared__ float red[256];
    __shared__ float swc2[DFFC];
    __shared__ uint64_t mbar[2];
    __shared__ int lastf;

    int tid = threadIdx.x, lane = tid & 31, wid = tid >> 5;
    int wm = wid >> 1, wn = wid & 1;          // 4(m) x 2(n) warp grid, warp tile 32x64
    int n0 = blockIdx.x * 128;
    int m0 = 0, cnt = 128;

    const __half* Asrc;
    const __half* Bsrc;
    int lda, ldb;
    if (MODE == 0) {
        Asrc = g_xh;  lda = DIN;  Bsrc = g_wpre; ldb = DFF;  m0 = blockIdx.y * 128;
    } else if (MODE == 1) {
        // in-kernel tile plan from g_cnt (all threads redundantly)
        int tile = blockIdx.y;
        int nt = 0, off = 0, t = -1, st0 = 0;
#pragma unroll
        for (int i = 0; i < NT; i++) {
            int ci = g_cnt[i];
            int nti = (ci + 127) >> 7;
            if (t < 0 && tile < nt + nti) {
                int j = tile - nt;
                t = i; st0 = off + j * 128; cnt = min(128, ci - j * 128);
            }
            nt += nti; off += ci;
        }
        if (t < 0) return;
        if (tid < 128) tok[tid] = g_perm[st0 + min(tid, cnt - 1)];
        Asrc = g_mid; lda = DFF;  Bsrc = g_wtyp + (size_t)t * DFF * DIN; ldb = DIN;
    } else {
        Asrc = g_xnew; lda = DIN; Bsrc = g_wc1; ldb = DFFC; m0 = blockIdx.y * 128;
        for (int i = tid; i < DFFC; i += 256) swc2[i] = wc2[i];
    }

    uint32_t sA = smem_u32(smA), sB = smem_u32(smB);
    uint32_t mb0 = smem_u32(&mbar[0]), mb1 = smem_u32(&mbar[1]);

    if (tid == 0) { MBAR_INIT(mb0, 1); MBAR_INIT(mb1, 1); }
    __syncthreads();   // tok[], swc2, mbarrier init all visible

    // one bulk copy per producer thread: tid<128 -> A row, 128<=tid<192 -> B k-row
    auto loadAB = [&](int stg, int kt) {
        uint32_t mb = stg ? mb1 : mb0;
        if (tid == 0) MBAR_EXPECT(mb, STAGE_BYTES);
        if (tid < 128) {
            int row = (MODE == 1) ? tok[tid] : (m0 + tid);
            bulkcp(sA + (uint32_t)(stg * STA + tid * RSA) * 2,
                   Asrc + (size_t)row * lda + kt * KT, 128, mb);
        } else if (tid < 192) {
            int r = tid - 128;
            bulkcp(sB + (uint32_t)(stg * STB + r * RSB) * 2,
                   Bsrc + (size_t)(kt * KT + r) * ldb + n0, 256, mb);
        }
    };

    float acc[2][8][4];
#pragma unroll
    for (int mi = 0; mi < 2; mi++)
#pragma unroll
        for (int ni = 0; ni < 8; ni++)
#pragma unroll
            for (int e = 0; e < 4; e++) acc[mi][ni][e] = 0.f;

    loadAB(0, 0);
    loadAB(1, 1);

    int arow0 = wm * 32 + (lane & 15);
    uint32_t acol = (uint32_t)((lane >> 4) << 3) * 2;
    int brow = lane & 15;
    uint32_t bcolh = (uint32_t)(wn * 64 + ((lane >> 4) << 3)) * 2;

    for (int kt = 0; kt < NK; kt++) {
        int st = kt & 1;
        MBAR_WAIT(st ? mb1 : mb0, (kt >> 1) & 1);   // acquire: bulk data visible
        uint32_t aB = sA + (uint32_t)(st * STA) * 2;
        uint32_t bB = sB + (uint32_t)(st * STB) * 2;

        uint32_t af[2][2][4];   // [ks&1][mi][4]
#pragma unroll
        for (int mi = 0; mi < 2; mi++)
            ldsm4(af[0][mi], aB + (uint32_t)((arow0 + mi * 16) * RSA) * 2 + acol);

#pragma unroll
        for (int ks = 0; ks < 4; ks++) {
            if (ks < 3) {
#pragma unroll
                for (int mi = 0; mi < 2; mi++)
                    ldsm4(af[(ks + 1) & 1][mi],
                          aB + (uint32_t)((arow0 + mi * 16) * RSA + (ks + 1) * 16) * 2 + acol);
            }
            uint32_t bRow = bB + (uint32_t)((ks * 16 + brow) * RSB) * 2 + bcolh;
#pragma unroll
            for (int nb = 0; nb < 4; nb++) {
                uint32_t t4[4];
                ldsm4t(t4, bRow + (uint32_t)(nb * 16) * 2);
#pragma unroll
                for (int mi = 0; mi < 2; mi++) {
                    mma16816(acc[mi][nb * 2],     af[ks & 1][mi], t4);
                    mma16816(acc[mi][nb * 2 + 1], af[ks & 1][mi], t4 + 2);
                }
            }
        }
        __syncthreads();                       // all warps done reading stage st
        if (kt + 2 < NK) loadAB(st, kt + 2);   // refill it
    }

    // ---- epilogues ----
    if (MODE == 2) {
#pragma unroll
        for (int mi = 0; mi < 2; mi++) {
#pragma unroll
            for (int hf = 0; hf < 2; hf++) {
                float p = 0.f;
#pragma unroll
                for (int ni = 0; ni < 8; ni++) {
                    int col = n0 + wn * 64 + ni * 8 + 2 * (lane & 3);
                    p += fmaxf(acc[mi][ni][hf * 2], 0.f) * swc2[col]
                       + fmaxf(acc[mi][ni][hf * 2 + 1], 0.f) * swc2[col + 1];
                }
                p += __shfl_xor_sync(0xFFFFFFFFu, p, 1);
                p += __shfl_xor_sync(0xFFFFFFFFu, p, 2);
                if ((lane & 3) == 0)
                    red[wn * 128 + wm * 32 + mi * 16 + hf * 8 + (lane >> 2)] = p;
            }
        }
        __syncthreads();
        if (tid < 128)
            g_part[(size_t)(m0 + tid) * 4 + blockIdx.x] = red[tid] + red[128 + tid];
        // ticket: last of the 4 N-CTAs for this M-tile sums partials (fixed order -> deterministic)
        __threadfence();
        __syncthreads();
        if (tid == 0) lastf = (atomicAdd(&g_tick[blockIdx.y], 1) == 3);
        __syncthreads();
        if (lastf) {
            __threadfence();
            if (tid < 128) {
                int r = m0 + tid;
                float4 p = ((const float4*)g_part)[r];
                out[r] = (p.x + p.y) + (p.z + p.w);
            }
        }
    } else {
#pragma unroll
        for (int mi = 0; mi < 2; mi++) {
#pragma unroll
            for (int hf = 0; hf < 2; hf++) {
                int lr = wm * 32 + mi * 16 + (lane >> 2) + hf * 8;
#pragma unroll
                for (int ni = 0; ni < 8; ni++) {
                    float d0 = acc[mi][ni][hf * 2], d1 = acc[mi][ni][hf * 2 + 1];
                    int col = n0 + wn * 64 + ni * 8 + 2 * (lane & 3);
                    if (MODE == 0) {
                        __half2 v = __floats2half2_rn(fmaxf(d0, 0.f), fmaxf(d1, 0.f));
                        *(__half2*)(g_mid + (size_t)(m0 + lr) * DFF + col) = v;
                    } else {
                        if (lr < cnt) {
                            int tk = tok[lr];
                            float2 xv = *(const float2*)(x + (size_t)tk * DIN + col);
                            __half2 v = __floats2half2_rn(xv.x + fmaxf(d0, 0.f),
                                                          xv.y + fmaxf(d1, 0.f));
                            *(__half2*)(g_xnew + (size_t)tk * DIN + col) = v;
                        }
                    }
                }
            }
        }
    }
}

// ---------------- launch ----------------
extern "C" void kernel_launch(void* const* d_in, const int* in_sizes, int n_in,
                              void* d_out, int out_size) {
    const float* x    = (const float*)d_in[0];
    const int*   typ  = (const int*)d_in[1];
    const float* Wpre = (const float*)d_in[2];
    const float* Wtyp = (const float*)d_in[3];
    const float* Wc1  = (const float*)d_in[4];
    const float* Wc2  = (const float*)d_in[5];
    float* out = (float*)d_out;

    cudaFuncSetAttribute(gemm_kernel<0, 8>,  cudaFuncAttributeMaxDynamicSharedMemorySize, SMEM_DYN);
    cudaFuncSetAttribute(gemm_kernel<1, 16>, cudaFuncAttributeMaxDynamicSharedMemorySize, SMEM_DYN);
    cudaFuncSetAttribute(gemm_kernel<2, 8>,  cudaFuncAttributeMaxDynamicSharedMemorySize, SMEM_DYN);

    prep_kernel<<<2048, 256>>>(x, Wpre, Wtyp, Wc1, typ);
    scatter_kernel<<<128, 256>>>(typ);

    gemm_kernel<0, 8><<<dim3(8, 256), 256, SMEM_DYN>>>(x, Wc2, out);        // mid
    gemm_kernel<1, 16><<<dim3(4, MAXTILES), 256, SMEM_DYN>>>(x, Wc2, out);  // routed + residual
    gemm_kernel<2, 8><<<dim3(4, 256), 256, SMEM_DYN>>>(x, Wc2, out);        // fused GEMV + out
}

// round 14
// speedup vs baseline: 1.2003x; 1.2003x over previous
#include <cuda_runtime.h>
#include <cuda_fp16.h>
#include <cstdint>

// ---------------- problem constants ----------------
#define NTOK 32768
#define DIN  512
#define DFF  1024
#define DFFC 512
#define NT   8
#define MAXTILES 264

#define KT  64           // K-tile in halves
#define RSA 72           // A smem row stride (halves)
#define RSB 136          // B smem row stride (halves)
#define STA (128 * RSA)  // halves per A stage  (9216)
#define STB (64 * RSB)   // halves per B stage  (8704)
#define SMEM_DYN (2 * (STA + STB) * 2)   // 71680 bytes -> 2 CTA/SM

// ---------------- device scratch ----------------
__device__ __half g_xh  [NTOK * DIN];        // x fp16
__device__ __half g_wpre[DIN * DFF];         // W_pre fp16 (natural [k][n])
__device__ __half g_wtyp[NT * DFF * DIN];    // W_types fp16 (natural [t][k][n])
__device__ __half g_wc1 [DIN * DFFC];        // W_c1 fp16 (natural [k][n])
__device__ __half g_mid [NTOK * DFF];        // relu(x @ W_pre)
__device__ __half g_xnew[NTOK * DIN];        // x + relu(mid @ Wt)
__device__ float  g_part[NTOK * 4];          // per-N-slice partial dots
__device__ int    g_perm[NTOK];
__device__ int    g_cnt[NT], g_cursor[NT];
__device__ int    g_tick[256];               // gemm2 per-M-tile completion tickets

// ---------------- helpers ----------------
static __device__ __forceinline__ uint32_t smem_u32(const void* p) {
    uint32_t a;
    asm("{ .reg .u64 t; cvta.to.shared.u64 t, %1; cvt.u32.u64 %0, t; }" : "=r"(a) : "l"(p));
    return a;
}
static __device__ __forceinline__ void cpasync16(uint32_t s, const void* g) {
    asm volatile("cp.async.cg.shared.global [%0], [%1], 16;" :: "r"(s), "l"(g));
}
#define CP_COMMIT() asm volatile("cp.async.commit_group;" ::: "memory")
#define CP_WAIT1()  asm volatile("cp.async.wait_group 1;" ::: "memory")

static __device__ __forceinline__ void ldsm4(uint32_t* r, uint32_t a) {
    asm volatile("ldmatrix.sync.aligned.m8n8.x4.shared.b16 {%0,%1,%2,%3}, [%4];"
                 : "=r"(r[0]), "=r"(r[1]), "=r"(r[2]), "=r"(r[3]) : "r"(a));
}
static __device__ __forceinline__ void ldsm4t(uint32_t* r, uint32_t a) {
    asm volatile("ldmatrix.sync.aligned.m8n8.x4.trans.shared.b16 {%0,%1,%2,%3}, [%4];"
                 : "=r"(r[0]), "=r"(r[1]), "=r"(r[2]), "=r"(r[3]) : "r"(a));
}
static __device__ __forceinline__ void mma16816(float* d, const uint32_t* a, const uint32_t* b) {
    asm volatile("mma.sync.aligned.m16n8k16.row.col.f32.f16.f16.f32 "
                 "{%0,%1,%2,%3}, {%4,%5,%6,%7}, {%8,%9}, {%0,%1,%2,%3};"
                 : "+f"(d[0]), "+f"(d[1]), "+f"(d[2]), "+f"(d[3])
                 : "r"(a[0]), "r"(a[1]), "r"(a[2]), "r"(a[3]), "r"(b[0]), "r"(b[1]));
}

// ---------------- prep: fp32 -> fp16 converts + histogram ----------------
__global__ void prep_kernel(const float* __restrict__ x, const float* __restrict__ wp,
                            const float* __restrict__ wt, const float* __restrict__ wc,
                            const int* __restrict__ tr) {
    __shared__ int cnt[NT];
    __shared__ int det;
    int tid = threadIdx.x;
    int g = blockIdx.x * blockDim.x + tid;
    int nth = gridDim.x * blockDim.x;
    if (g < NT) { g_cnt[g] = 0; g_cursor[g] = 0; }
    if (g < 256) g_tick[g] = 0;

    if (blockIdx.x < 128) {
        if (tid < NT) cnt[tid] = 0;
        if (tid == 0) det = 0;
        __syncthreads();
        // dtype sniff: int64 (LE) => odd int32 words are all zero (types < 8)
        if (tr[2 * tid + 1]) atomicOr(&det, 1);
        __syncthreads();
        int stride = det ? 1 : 2;
        int i = blockIdx.x * 256 + tid;
        atomicAdd(&cnt[tr[i * stride] & 7], 1);
        __syncthreads();
        if (tid < NT) atomicAdd(&g_cnt[tid], cnt[tid]);
    }

    for (int i = g; i < NTOK * DIN / 4; i += nth) {
        float4 v = ((const float4*)x)[i];
        ((__half2*)g_xh)[2 * i]     = __floats2half2_rn(v.x, v.y);
        ((__half2*)g_xh)[2 * i + 1] = __floats2half2_rn(v.z, v.w);
    }
    for (int i = g; i < DIN * DFF / 4; i += nth) {
        float4 v = ((const float4*)wp)[i];
        ((__half2*)g_wpre)[2 * i]     = __floats2half2_rn(v.x, v.y);
        ((__half2*)g_wpre)[2 * i + 1] = __floats2half2_rn(v.z, v.w);
    }
    for (int i = g; i < NT * DFF * DIN / 4; i += nth) {
        float4 v = ((const float4*)wt)[i];
        ((__half2*)g_wtyp)[2 * i]     = __floats2half2_rn(v.x, v.y);
        ((__half2*)g_wtyp)[2 * i + 1] = __floats2half2_rn(v.z, v.w);
    }
    for (int i = g; i < DIN * DFFC / 4; i += nth) {
        float4 v = ((const float4*)wc)[i];
        ((__half2*)g_wc1)[2 * i]     = __floats2half2_rn(v.x, v.y);
        ((__half2*)g_wc1)[2 * i + 1] = __floats2half2_rn(v.z, v.w);
    }
}

__global__ void scatter_kernel(const int* __restrict__ tr) {  // grid 128 x 256
    __shared__ int cnt[NT], base[NT];
    __shared__ int det;
    int tid = threadIdx.x;
    if (tid < NT) cnt[tid] = 0;
    if (tid == 0) det = 0;
    __syncthreads();
    if (tr[2 * tid + 1]) atomicOr(&det, 1);
    __syncthreads();
    int stride = det ? 1 : 2;
    int i = blockIdx.x * 256 + tid;
    int t = tr[i * stride] & 7;
    int ls = atomicAdd(&cnt[t], 1);
    __syncthreads();
    if (tid < NT) {
        int pre = 0;
#pragma unroll
        for (int j = 0; j < NT; j++) if (j < tid) pre += g_cnt[j];
        base[tid] = pre + atomicAdd(&g_cursor[tid], cnt[tid]);
    }
    __syncthreads();
    g_perm[base[t] + ls] = i;
}

// ---------------- 128x128 tile GEMM, 8 warps of 32x64, 2-stage (R10 pipeline) ----------------
// MODE 0: mid  = relu(xh @ wpre)            NK=8,  N=1024
// MODE 1: xnew = x + relu(mid_g @ wtyp[t])  NK=16, N=512, gathered rows (in-kernel plan)
// MODE 2: fused GEMV + ticketed final sum   NK=8,  N=512
template<int MODE, int NK>
__global__ void __launch_bounds__(256, 2) gemm_kernel(const float* __restrict__ x,
                                                      const float* __restrict__ wc2,
                                                      float* __restrict__ out) {
    extern __shared__ __half smem[];
    __half* smA = smem;             // [2][STA]
    __half* smB = smem + 2 * STA;   // [2][STB]
    __shared__ int tok[128];
    __shared__ float red[256];
    __shared__ float swc2[DFFC];
    __shared__ int lastf;

    int tid = threadIdx.x, lane = tid & 31, wid = tid >> 5;
    int wm = wid >> 1, wn = wid & 1;          // 4(m) x 2(n) warp grid, warp tile 32x64
    int n0 = blockIdx.x * 128;
    int m0 = 0, cnt = 128;

    const __half* Asrc;
    const __half* Bsrc;
    int lda, ldb;
    if (MODE == 0) {
        Asrc = g_xh;  lda = DIN;  Bsrc = g_wpre; ldb = DFF;  m0 = blockIdx.y * 128;
    } else if (MODE == 1) {
        // in-kernel tile plan from g_cnt (all threads redundantly)
        int tile = blockIdx.y;
        int nt = 0, off = 0, t = -1, st0 = 0;
#pragma unroll
        for (int i = 0; i < NT; i++) {
            int ci = g_cnt[i];
            int nti = (ci + 127) >> 7;
            if (t < 0 && tile < nt + nti) {
                int j = tile - nt;
                t = i; st0 = off + j * 128; cnt = min(128, ci - j * 128);
            }
            nt += nti; off += ci;
        }
        if (t < 0) return;
        if (tid < 128) tok[tid] = g_perm[st0 + min(tid, cnt - 1)];
        Asrc = g_mid; lda = DFF;  Bsrc = g_wtyp + (size_t)t * DFF * DIN; ldb = DIN;
        __syncthreads();
    } else {
        Asrc = g_xnew; lda = DIN; Bsrc = g_wc1; ldb = DFFC; m0 = blockIdx.y * 128;
        for (int i = tid; i < DFFC; i += 256) swc2[i] = wc2[i];
    }

    uint32_t sA = smem_u32(smA), sB = smem_u32(smB);

    auto loadA = [&](int stg, int kt) {
#pragma unroll
        for (int i = tid; i < 1024; i += 256) {   // 128 rows x 8 chunks(16B)
            int r = i >> 3, c = i & 7;
            int row = (MODE == 1) ? tok[r] : (m0 + r);
            cpasync16(sA + (uint32_t)(stg * STA + r * RSA + c * 8) * 2,
                      Asrc + (size_t)row * lda + kt * KT + c * 8);
        }
    };
    auto loadB = [&](int stg, int kt) {
#pragma unroll
        for (int i = tid; i < 1024; i += 256) {   // 64 k-rows x 16 chunks(16B)
            int r = i >> 4, c = i & 15;
            cpasync16(sB + (uint32_t)(stg * STB + r * RSB + c * 8) * 2,
                      Bsrc + (size_t)(kt * KT + r) * ldb + n0 + c * 8);
        }
    };

    float acc[2][8][4];
#pragma unroll
    for (int mi = 0; mi < 2; mi++)
#pragma unroll
        for (int ni = 0; ni < 8; ni++)
#pragma unroll
            for (int e = 0; e < 4; e++) acc[mi][ni][e] = 0.f;

    loadA(0, 0); loadB(0, 0); CP_COMMIT();
    loadA(1, 1); loadB(1, 1); CP_COMMIT();

    // A-fragment addresses: per-warp bases; af double-buffered on ks parity.
    int arow0 = wm * 32 + (lane & 15);
    uint32_t acol = (uint32_t)((lane >> 4) << 3) * 2;
    int brow = lane & 15;
    uint32_t bcolh = (uint32_t)(wn * 64 + ((lane >> 4) << 3)) * 2;

    for (int kt = 0; kt < NK; kt++) {
        CP_WAIT1();
        __syncthreads();
        int st = kt & 1;
        uint32_t aB = sA + (uint32_t)(st * STA) * 2;
        uint32_t bB = sB + (uint32_t)(st * STB) * 2;

        uint32_t af[2][2][4];   // [ks&1][mi][4]
#pragma unroll
        for (int mi = 0; mi < 2; mi++)
            ldsm4(af[0][mi], aB + (uint32_t)((arow0 + mi * 16) * RSA) * 2 + acol);

#pragma unroll
        for (int ks = 0; ks < 4; ks++) {
            if (ks < 3) {
#pragma unroll
                for (int mi = 0; mi < 2; mi++)
                    ldsm4(af[(ks + 1) & 1][mi],
                          aB + (uint32_t)((arow0 + mi * 16) * RSA + (ks + 1) * 16) * 2 + acol);
            }
            uint32_t bRow = bB + (uint32_t)((ks * 16 + brow) * RSB) * 2 + bcolh;
#pragma unroll
            for (int nb = 0; nb < 4; nb++) {
                uint32_t t4[4];
                ldsm4t(t4, bRow + (uint32_t)(nb * 16) * 2);
#pragma unroll
                for (int mi = 0; mi < 2; mi++) {
                    mma16816(acc[mi][nb * 2],     af[ks & 1][mi], t4);
                    mma16816(acc[mi][nb * 2 + 1], af[ks & 1][mi], t4 + 2);
                }
            }
        }
        __syncthreads();
        if (kt + 2 < NK) { loadA(st, kt + 2); loadB(st, kt + 2); }
        CP_COMMIT();
    }

    // ---- epilogues ----
    if (MODE == 2) {
#pragma unroll
        for (int mi = 0; mi < 2; mi++) {
#pragma unroll
            for (int hf = 0; hf < 2; hf++) {
                float p = 0.f;
#pragma unroll
                for (int ni = 0; ni < 8; ni++) {
                    int col = n0 + wn * 64 + ni * 8 + 2 * (lane & 3);
                    p += fmaxf(acc[mi][ni][hf * 2], 0.f) * swc2[col]
                       + fmaxf(acc[mi][ni][hf * 2 + 1], 0.f) * swc2[col + 1];
                }
                p += __shfl_xor_sync(0xFFFFFFFFu, p, 1);
                p += __shfl_xor_sync(0xFFFFFFFFu, p, 2);
                if ((lane & 3) == 0)
                    red[wn * 128 + wm * 32 + mi * 16 + hf * 8 + (lane >> 2)] = p;
            }
        }
        __syncthreads();
        if (tid < 128)
            g_part[(size_t)(m0 + tid) * 4 + blockIdx.x] = red[tid] + red[128 + tid];
        // ticket: last of the 4 N-CTAs for this M-tile sums partials (fixed order -> deterministic)
        __threadfence();
        __syncthreads();
        if (tid == 0) lastf = (atomicAdd(&g_tick[blockIdx.y], 1) == 3);
        __syncthreads();
        if (lastf) {
            __threadfence();
            if (tid < 128) {
                int r = m0 + tid;
                float4 p = ((const float4*)g_part)[r];
                out[r] = (p.x + p.y) + (p.z + p.w);
            }
        }
    } else {
#pragma unroll
        for (int mi = 0; mi < 2; mi++) {
#pragma unroll
            for (int hf = 0; hf < 2; hf++) {
                int lr = wm * 32 + mi * 16 + (lane >> 2) + hf * 8;
#pragma unroll
                for (int ni = 0; ni < 8; ni++) {
                    float d0 = acc[mi][ni][hf * 2], d1 = acc[mi][ni][hf * 2 + 1];
                    int col = n0 + wn * 64 + ni * 8 + 2 * (lane & 3);
                    if (MODE == 0) {
                        __half2 v = __floats2half2_rn(fmaxf(d0, 0.f), fmaxf(d1, 0.f));
                        *(__half2*)(g_mid + (size_t)(m0 + lr) * DFF + col) = v;
                    } else {
                        if (lr < cnt) {
                            int tk = tok[lr];
                            float2 xv = *(const float2*)(x + (size_t)tk * DIN + col);
                            __half2 v = __floats2half2_rn(xv.x + fmaxf(d0, 0.f),
                                                          xv.y + fmaxf(d1, 0.f));
                            *(__half2*)(g_xnew + (size_t)tk * DIN + col) = v;
                        }
                    }
                }
            }
        }
    }
}

// ---------------- launch ----------------
extern "C" void kernel_launch(void* const* d_in, const int* in_sizes, int n_in,
                              void* d_out, int out_size) {
    const float* x    = (const float*)d_in[0];
    const int*   typ  = (const int*)d_in[1];
    const float* Wpre = (const float*)d_in[2];
    const float* Wtyp = (const float*)d_in[3];
    const float* Wc1  = (const float*)d_in[4];
    const float* Wc2  = (const float*)d_in[5];
    float* out = (float*)d_out;

    cudaFuncSetAttribute(gemm_kernel<0, 8>,  cudaFuncAttributeMaxDynamicSharedMemorySize, SMEM_DYN);
    cudaFuncSetAttribute(gemm_kernel<1, 16>, cudaFuncAttributeMaxDynamicSharedMemorySize, SMEM_DYN);
    cudaFuncSetAttribute(gemm_kernel<2, 8>,  cudaFuncAttributeMaxDynamicSharedMemorySize, SMEM_DYN);

    prep_kernel<<<2048, 256>>>(x, Wpre, Wtyp, Wc1, typ);
    scatter_kernel<<<128, 256>>>(typ);

    gemm_kernel<0, 8><<<dim3(8, 256), 256, SMEM_DYN>>>(x, Wc2, out);        // mid
    gemm_kernel<1, 16><<<dim3(4, MAXTILES), 256, SMEM_DYN>>>(x, Wc2, out);  // routed + residual
    gemm_kernel<2, 8><<<dim3(4, 256), 256, SMEM_DYN>>>(x, Wc2, out);        // fused GEMV + out
}

// round 17
// speedup vs baseline: 1.2019x; 1.0013x over previous
#include <cuda_runtime.h>
#include <cuda_fp16.h>
#include <cstdint>

// ---------------- problem constants ----------------
#define NTOK 32768
#define DIN  512
#define DFF  1024
#define DFFC 512
#define NT   8
#define MAXTILES 264

#define KT  64           // K-tile in halves
#define RSA 72           // A smem row stride (halves)
#define RSB 136          // B smem row stride (halves)
#define STA (128 * RSA)  // halves per A stage  (9216)
#define STB (64 * RSB)   // halves per B stage  (8704)
#define SMEM_DYN (2 * (STA + STB) * 2)   // 71680 bytes -> 2 CTA/SM

// ---------------- device scratch ----------------
__device__ __half g_xh  [NTOK * DIN];        // x fp16
__device__ __half g_wpre[DIN * DFF];         // W_pre fp16 (natural [k][n])
__device__ __half g_wtyp[NT * DFF * DIN];    // W_types fp16 (natural [t][k][n])
__device__ __half g_wc1 [DIN * DFFC];        // W_c1 fp16 (natural [k][n])
__device__ __half g_mid [NTOK * DFF];        // relu(x @ W_pre)
__device__ __half g_xnew[NTOK * DIN];        // x + relu(mid @ Wt)
__device__ float  g_part[NTOK * 4];          // per-N-slice partial dots
__device__ int    g_perm[NTOK];
__device__ int    g_cnt[NT], g_cursor[NT];
__device__ int    g_tick[256];               // gemm2 per-M-tile completion tickets

// ---------------- helpers ----------------
static __device__ __forceinline__ uint32_t smem_u32(const void* p) {
    uint32_t a;
    asm("{ .reg .u64 t; cvta.to.shared.u64 t, %1; cvt.u32.u64 %0, t; }" : "=r"(a) : "l"(p));
    return a;
}
static __device__ __forceinline__ void cpasync16(uint32_t s, const void* g) {
    asm volatile("cp.async.cg.shared.global [%0], [%1], 16;" :: "r"(s), "l"(g));
}
// async arrive on mbar when all this thread's prior cp.async ops complete.
// .noinc: counts against the barrier's init count (CUTLASS pattern) — the
// default (inc) form self-cancels and deadlocks (R16 post-mortem).
static __device__ __forceinline__ void cp_mbar_arrive(uint32_t mb) {
    asm volatile("cp.async.mbarrier.arrive.noinc.shared::cta.b64 [%0];" :: "r"(mb) : "memory");
}
#define MBAR_INIT(mb, c) \
    asm volatile("mbarrier.init.shared.b64 [%0], %1;" :: "r"((uint32_t)(mb)), "r"((uint32_t)(c)) : "memory")
#define MBAR_WAIT(mb, ph) do { \
    uint32_t _m = (uint32_t)(mb); uint32_t _p = (uint32_t)(ph); uint32_t _d; \
    asm volatile("{\n\t.reg .pred p;\n\t" \
        "mbarrier.try_wait.parity.acquire.cta.shared::cta.b64 p, [%1], %2;\n\t" \
        "selp.b32 %0, 1, 0, p;\n\t}" : "=r"(_d) : "r"(_m), "r"(_p) : "memory"); \
    if (!_d) { \
        asm volatile("{\n\t.reg .pred P1;\n\t" \
            "WL_%=:\n\t" \
            "mbarrier.try_wait.parity.acquire.cta.shared::cta.b64 P1, [%0], %1, 0x989680;\n\t" \
            "@P1 bra.uni WD_%=;\n\t" \
            "bra.uni WL_%=;\n\t" \
            "WD_%=:\n\t}" :: "r"(_m), "r"(_p) : "memory"); \
    } } while (0)

static __device__ __forceinline__ void ldsm4(uint32_t* r, uint32_t a) {
    asm volatile("ldmatrix.sync.aligned.m8n8.x4.shared.b16 {%0,%1,%2,%3}, [%4];"
                 : "=r"(r[0]), "=r"(r[1]), "=r"(r[2]), "=r"(r[3]) : "r"(a));
}
static __device__ __forceinline__ void ldsm4t(uint32_t* r, uint32_t a) {
    asm volatile("ldmatrix.sync.aligned.m8n8.x4.trans.shared.b16 {%0,%1,%2,%3}, [%4];"
                 : "=r"(r[0]), "=r"(r[1]), "=r"(r[2]), "=r"(r[3]) : "r"(a));
}
static __device__ __forceinline__ void mma16816(float* d, const uint32_t* a, const uint32_t* b) {
    asm volatile("mma.sync.aligned.m16n8k16.row.col.f32.f16.f16.f32 "
                 "{%0,%1,%2,%3}, {%4,%5,%6,%7}, {%8,%9}, {%0,%1,%2,%3};"
                 : "+f"(d[0]), "+f"(d[1]), "+f"(d[2]), "+f"(d[3])
                 : "r"(a[0]), "r"(a[1]), "r"(a[2]), "r"(a[3]), "r"(b[0]), "r"(b[1]));
}

// ---------------- prep: fp32 -> fp16 converts + histogram ----------------
__global__ void prep_kernel(const float* __restrict__ x, const float* __restrict__ wp,
                            const float* __restrict__ wt, const float* __restrict__ wc,
                            const int* __restrict__ tr) {
    __shared__ int cnt[NT];
    __shared__ int det;
    int tid = threadIdx.x;
    int g = blockIdx.x * blockDim.x + tid;
    int nth = gridDim.x * blockDim.x;
    if (g < NT) { g_cnt[g] = 0; g_cursor[g] = 0; }
    if (g < 256) g_tick[g] = 0;

    if (blockIdx.x < 128) {
        if (tid < NT) cnt[tid] = 0;
        if (tid == 0) det = 0;
        __syncthreads();
        // dtype sniff: int64 (LE) => odd int32 words are all zero (types < 8)
        if (tr[2 * tid + 1]) atomicOr(&det, 1);
        __syncthreads();
        int stride = det ? 1 : 2;
        int i = blockIdx.x * 256 + tid;
        atomicAdd(&cnt[tr[i * stride] & 7], 1);
        __syncthreads();
        if (tid < NT) atomicAdd(&g_cnt[tid], cnt[tid]);
    }

    for (int i = g; i < NTOK * DIN / 4; i += nth) {
        float4 v = ((const float4*)x)[i];
        ((__half2*)g_xh)[2 * i]     = __floats2half2_rn(v.x, v.y);
        ((__half2*)g_xh)[2 * i + 1] = __floats2half2_rn(v.z, v.w);
    }
    for (int i = g; i < DIN * DFF / 4; i += nth) {
        float4 v = ((const float4*)wp)[i];
        ((__half2*)g_wpre)[2 * i]     = __floats2half2_rn(v.x, v.y);
        ((__half2*)g_wpre)[2 * i + 1] = __floats2half2_rn(v.z, v.w);
    }
    for (int i = g; i < NT * DFF * DIN / 4; i += nth) {
        float4 v = ((const float4*)wt)[i];
        ((__half2*)g_wtyp)[2 * i]     = __floats2half2_rn(v.x, v.y);
        ((__half2*)g_wtyp)[2 * i + 1] = __floats2half2_rn(v.z, v.w);
    }
    for (int i = g; i < DIN * DFFC / 4; i += nth) {
        float4 v = ((const float4*)wc)[i];
        ((__half2*)g_wc1)[2 * i]     = __floats2half2_rn(v.x, v.y);
        ((__half2*)g_wc1)[2 * i + 1] = __floats2half2_rn(v.z, v.w);
    }
}

__global__ void scatter_kernel(const int* __restrict__ tr) {  // grid 128 x 256
    __shared__ int cnt[NT], base[NT];
    __shared__ int det;
    int tid = threadIdx.x;
    if (tid < NT) cnt[tid] = 0;
    if (tid == 0) det = 0;
    __syncthreads();
    if (tr[2 * tid + 1]) atomicOr(&det, 1);
    __syncthreads();
    int stride = det ? 1 : 2;
    int i = blockIdx.x * 256 + tid;
    int t = tr[i * stride] & 7;
    int ls = atomicAdd(&cnt[t], 1);
    __syncthreads();
    if (tid < NT) {
        int pre = 0;
#pragma unroll
        for (int j = 0; j < NT; j++) if (j < tid) pre += g_cnt[j];
        base[tid] = pre + atomicAdd(&g_cursor[tid], cnt[tid]);
    }
    __syncthreads();
    g_perm[base[t] + ls] = i;
}

// ---------------- 128x128 tile GEMM, 8 warps of 32x64, 2-stage, mbar-completed cp.async ----------------
// MODE 0: mid  = relu(xh @ wpre)            NK=8,  N=1024
// MODE 1: xnew = x + relu(mid_g @ wtyp[t])  NK=16, N=512, gathered rows (in-kernel plan)
// MODE 2: fused GEMV + ticketed final sum   NK=8,  N=512
template<int MODE, int NK>
__global__ void __launch_bounds__(256, 2) gemm_kernel(const float* __restrict__ x,
                                                      const float* __restrict__ wc2,
                                                      float* __restrict__ out) {
    extern __shared__ __half smem[];
    __half* smA = smem;             // [2][STA]
    __half* smB = smem + 2 * STA;   // [2][STB]
    __shared__ int tok[128];
    __shared__ float red[256];
    __shared__ float swc2[DFFC];
    __shared__ uint64_t fullmb[2];
    __shared__ int lastf;

    int tid = threadIdx.x, lane = tid & 31, wid = tid >> 5;
    int wm = wid >> 1, wn = wid & 1;          // 4(m) x 2(n) warp grid, warp tile 32x64
    int n0 = blockIdx.x * 128;
    int m0 = 0, cnt = 128;

    const __half* Asrc;
    const __half* Bsrc;
    int lda, ldb;
    if (MODE == 0) {
        Asrc = g_xh;  lda = DIN;  Bsrc = g_wpre; ldb = DFF;  m0 = blockIdx.y * 128;
    } else if (MODE == 1) {
        // in-kernel tile plan from g_cnt (all threads redundantly)
        int tile = blockIdx.y;
        int nt = 0, off = 0, t = -1, st0 = 0;
#pragma unroll
        for (int i = 0; i < NT; i++) {
            int ci = g_cnt[i];
            int nti = (ci + 127) >> 7;
            if (t < 0 && tile < nt + nti) {
                int j = tile - nt;
                t = i; st0 = off + j * 128; cnt = min(128, ci - j * 128);
            }
            nt += nti; off += ci;
        }
        if (t < 0) return;
        if (tid < 128) tok[tid] = g_perm[st0 + min(tid, cnt - 1)];
        Asrc = g_mid; lda = DFF;  Bsrc = g_wtyp + (size_t)t * DFF * DIN; ldb = DIN;
    } else {
        Asrc = g_xnew; lda = DIN; Bsrc = g_wc1; ldb = DFFC; m0 = blockIdx.y * 128;
        for (int i = tid; i < DFFC; i += 256) swc2[i] = wc2[i];
    }

    uint32_t sA = smem_u32(smA), sB = smem_u32(smB);
    uint32_t mb0 = smem_u32(&fullmb[0]), mb1 = smem_u32(&fullmb[1]);
    if (tid == 0) { MBAR_INIT(mb0, 256); MBAR_INIT(mb1, 256); }
    __syncthreads();   // tok[] / swc2 / mbarrier init visible to all

    // each thread copies its slice, then async-arrives on the stage mbarrier
    auto loadAB = [&](int stg, int kt) {
#pragma unroll
        for (int i = tid; i < 1024; i += 256) {   // A: 128 rows x 8 chunks(16B)
            int r = i >> 3, c = i & 7;
            int row = (MODE == 1) ? tok[r] : (m0 + r);
            cpasync16(sA + (uint32_t)(stg * STA + r * RSA + c * 8) * 2,
                      Asrc + (size_t)row * lda + kt * KT + c * 8);
        }
#pragma unroll
        for (int i = tid; i < 1024; i += 256) {   // B: 64 k-rows x 16 chunks(16B)
            int r = i >> 4, c = i & 15;
            cpasync16(sB + (uint32_t)(stg * STB + r * RSB + c * 8) * 2,
                      Bsrc + (size_t)(kt * KT + r) * ldb + n0 + c * 8);
        }
        cp_mbar_arrive(stg ? mb1 : mb0);
    };

    float acc[2][8][4];
#pragma unroll
    for (int mi = 0; mi < 2; mi++)
#pragma unroll
        for (int ni = 0; ni < 8; ni++)
#pragma unroll
            for (int e = 0; e < 4; e++) acc[mi][ni][e] = 0.f;

    loadAB(0, 0);
    loadAB(1, 1);

    // A-fragment addresses: per-warp bases; af double-buffered on ks parity.
    int arow0 = wm * 32 + (lane & 15);
    uint32_t acol = (uint32_t)((lane >> 4) << 3) * 2;
    int brow = lane & 15;
    uint32_t bcolh = (uint32_t)(wn * 64 + ((lane >> 4) << 3)) * 2;

    for (int kt = 0; kt < NK; kt++) {
        int st = kt & 1;
        MBAR_WAIT(st ? mb1 : mb0, (kt >> 1) & 1);   // stage data complete (all 256 arrivals)
        uint32_t aB = sA + (uint32_t)(st * STA) * 2;
        uint32_t bB = sB + (uint32_t)(st * STB) * 2;

        uint32_t af[2][2][4];   // [ks&1][mi][4]
#pragma unroll
        for (int mi = 0; mi < 2; mi++)
            ldsm4(af[0][mi], aB + (uint32_t)((arow0 + mi * 16) * RSA) * 2 + acol);

#pragma unroll
        for (int ks = 0; ks < 4; ks++) {
            if (ks < 3) {
#pragma unroll
                for (int mi = 0; mi < 2; mi++)
                    ldsm4(af[(ks + 1) & 1][mi],
                          aB + (uint32_t)((arow0 + mi * 16) * RSA + (ks + 1) * 16) * 2 + acol);
            }
            uint32_t bRow = bB + (uint32_t)((ks * 16 + brow) * RSB) * 2 + bcolh;
#pragma unroll
            for (int nb = 0; nb < 4; nb++) {
                uint32_t t4[4];
                ldsm4t(t4, bRow + (uint32_t)(nb * 16) * 2);
#pragma unroll
                for (int mi = 0; mi < 2; mi++) {
                    mma16816(acc[mi][nb * 2],     af[ks & 1][mi], t4);
                    mma16816(acc[mi][nb * 2 + 1], af[ks & 1][mi], t4 + 2);
                }
            }
        }
        __syncthreads();                       // all warps done reading stage st
        if (kt + 2 < NK) loadAB(st, kt + 2);   // refill it, async-arrives on completion
    }

    // ---- epilogues ----
    if (MODE == 2) {
#pragma unroll
        for (int mi = 0; mi < 2; mi++) {
#pragma unroll
            for (int hf = 0; hf < 2; hf++) {
                float p = 0.f;
#pragma unroll
                for (int ni = 0; ni < 8; ni++) {
                    int col = n0 + wn * 64 + ni * 8 + 2 * (lane & 3);
                    p += fmaxf(acc[mi][ni][hf * 2], 0.f) * swc2[col]
                       + fmaxf(acc[mi][ni][hf * 2 + 1], 0.f) * swc2[col + 1];
                }
                p += __shfl_xor_sync(0xFFFFFFFFu, p, 1);
                p += __shfl_xor_sync(0xFFFFFFFFu, p, 2);
                if ((lane & 3) == 0)
                    red[wn * 128 + wm * 32 + mi * 16 + hf * 8 + (lane >> 2)] = p;
            }
        }
        __syncthreads();
        if (tid < 128)
            g_part[(size_t)(m0 + tid) * 4 + blockIdx.x] = red[tid] + red[128 + tid];
        // ticket: last of the 4 N-CTAs for this M-tile sums partials (fixed order -> deterministic)
        __threadfence();
        __syncthreads();
        if (tid == 0) lastf = (atomicAdd(&g_tick[blockIdx.y], 1) == 3);
        __syncthreads();
        if (lastf) {
            __threadfence();
            if (tid < 128) {
                int r = m0 + tid;
                float4 p = ((const float4*)g_part)[r];
                out[r] = (p.x + p.y) + (p.z + p.w);
            }
        }
    } else {
#pragma unroll
        for (int mi = 0; mi < 2; mi++) {
#pragma unroll
            for (int hf = 0; hf < 2; hf++) {
                int lr = wm * 32 + mi * 16 + (lane >> 2) + hf * 8;
#pragma unroll
                for (int ni = 0; ni < 8; ni++) {
                    float d0 = acc[mi][ni][hf * 2], d1 = acc[mi][ni][hf * 2 + 1];
                    int col = n0 + wn * 64 + ni * 8 + 2 * (lane & 3);
                    if (MODE == 0) {
                        __half2 v = __floats2half2_rn(fmaxf(d0, 0.f), fmaxf(d1, 0.f));
                        *(__half2*)(g_mid + (size_t)(m0 + lr) * DFF + col) = v;
                    } else {
                        if (lr < cnt) {
                            int tk = tok[lr];
                            float2 xv = *(const float2*)(x + (size_t)tk * DIN + col);
                            __half2 v = __floats2half2_rn(xv.x + fmaxf(d0, 0.f),
                                                          xv.y + fmaxf(d1, 0.f));
                            *(__half2*)(g_xnew + (size_t)tk * DIN + col) = v;
                        }
                    }
                }
            }
        }
    }
}

// ---------------- launch ----------------
extern "C" void kernel_launch(void* const* d_in, const int* in_sizes, int n_in,
                              void* d_out, int out_size) {
    const float* x    = (const float*)d_in[0];
    const int*   typ  = (const int*)d_in[1];
    const float* Wpre = (const float*)d_in[2];
    const float* Wtyp = (const float*)d_in[3];
    const float* Wc1  = (const float*)d_in[4];
    const float* Wc2  = (const float*)d_in[5];
    float* out = (float*)d_out;

    cudaFuncSetAttribute(gemm_kernel<0, 8>,  cudaFuncAttributeMaxDynamicSharedMemorySize, SMEM_DYN);
    cudaFuncSetAttribute(gemm_kernel<1, 16>, cudaFuncAttributeMaxDynamicSharedMemorySize, SMEM_DYN);
    cudaFuncSetAttribute(gemm_kernel<2, 8>,  cudaFuncAttributeMaxDynamicSharedMemorySize, SMEM_DYN);

    prep_kernel<<<2048, 256>>>(x, Wpre, Wtyp, Wc1, typ);
    scatter_kernel<<<128, 256>>>(typ);

    gemm_kernel<0, 8><<<dim3(8, 256), 256, SMEM_DYN>>>(x, Wc2, out);        // mid
    gemm_kernel<1, 16><<<dim3(4, MAXTILES), 256, SMEM_DYN>>>(x, Wc2, out);  // routed + residual
    gemm_kernel<2, 8><<<dim3(4, 256), 256, SMEM_DYN>>>(x, Wc2, out);        // fused GEMV + out
}